// round 4
// baseline (speedup 1.0000x reference)
#include <cuda_runtime.h>
#include <math.h>

#define FEAT    128
#define NRBF    20
#define NATOMS  8192
#define NEDGES  262144
#define NGRAPHS 128
#define APB     8

typedef unsigned long long ull;

// ---------------- f32x2 packed helpers ----------------
__device__ __forceinline__ ull f2pack(float lo, float hi) {
    ull r; asm("mov.b64 %0,{%1,%2};" : "=l"(r) : "f"(lo), "f"(hi)); return r;
}
__device__ __forceinline__ void f2unpack(ull p, float& a, float& b) {
    asm("mov.b64 {%0,%1},%2;" : "=f"(a), "=f"(b) : "l"(p));
}
__device__ __forceinline__ ull f2fma(ull a, ull b, ull c) {
    ull d; asm("fma.rn.f32x2 %0,%1,%2,%3;" : "=l"(d) : "l"(a), "l"(b), "l"(c)); return d;
}
__device__ __forceinline__ ull f2mul(ull a, ull b) {
    ull d; asm("mul.rn.f32x2 %0,%1,%2;" : "=l"(d) : "l"(a), "l"(b)); return d;
}

// ---------------- device scratch ----------------
__device__ float g_phi[NATOMS * 384];
__device__ float g_qkv[NATOMS * 384];
__device__ float g_h  [NATOMS * 128];
__device__ float g_vt [NATOMS * 384];
__device__ int   g_cnt[NATOMS];
__device__ int   g_off[NATOMS];
__device__ int   g_pos[NEDGES];
__device__ int   g_eid[NEDGES];

// ---------------- CSR build ----------------
__global__ void k_hist(const int2* __restrict__ nbrs) {
    int e = blockIdx.x * 256 + threadIdx.x;
    int2 nb = nbrs[e];
    g_pos[e] = atomicAdd(&g_cnt[nb.x], 1);
}
__global__ void k_scan() {
    __shared__ int sh[1024];
    int t = threadIdx.x;
    int c[8];
    int run = 0;
#pragma unroll
    for (int j = 0; j < 8; j++) { int v = g_cnt[t * 8 + j]; c[j] = run; run += v; }
    sh[t] = run;
    __syncthreads();
    for (int ofs = 1; ofs < 1024; ofs <<= 1) {
        int v = (t >= ofs) ? sh[t - ofs] : 0;
        __syncthreads();
        sh[t] += v;
        __syncthreads();
    }
    int excl = sh[t] - run;
#pragma unroll
    for (int j = 0; j < 8; j++) g_off[t * 8 + j] = excl + c[j];
}
// scatter (blocks 0..1023) + v transpose (blocks 1024..5119, 2 atoms each)
__global__ void __launch_bounds__(256)
k_sv(const int2* __restrict__ nbrs, const float* __restrict__ v) {
    int bid = blockIdx.x, tid = threadIdx.x;
    if (bid < 1024) {
        int e = bid * 256 + tid;
        int2 nb = nbrs[e];
        g_eid[g_off[nb.x] + g_pos[e]] = e;
    } else {
        int atom = (bid - 1024) * 2 + (tid >> 7);
        int cc = tid & 127;
        const float* p = v + ((size_t)atom * FEAT + cc) * 3;
        float x = p[0], y = p[1], z = p[2];
        g_vt[(size_t)atom * 384 + cc]       = x;
        g_vt[(size_t)atom * 384 + 128 + cc] = y;
        g_vt[(size_t)atom * 384 + 256 + cc] = z;
    }
}

// ---------------- SGEMM core (64x64 tile, f32x2) ----------------
__device__ __forceinline__ void gemm_tile(
    const float* __restrict__ A, const float* __restrict__ B,
    const float* __restrict__ bias, float* __restrict__ C,
    int K, int N, int act, int bx, int by,
    float As[16][68], float Bs[16][68])
{
    const int tid = threadIdx.x;
    const int tx = tid & 15, ty = tid >> 4;
    const int ar = tid >> 2, aq = tid & 3;
    const int bk = tid >> 4, bc = (tid & 15) * 4;

    ull acc[4][2];
#pragma unroll
    for (int r = 0; r < 4; r++) { acc[r][0] = 0ull; acc[r][1] = 0ull; }

    for (int k0 = 0; k0 < K; k0 += 16) {
        __syncthreads();
        float4 av = *(const float4*)&A[(size_t)(by + ar) * K + k0 + aq * 4];
        As[aq * 4 + 0][ar] = av.x; As[aq * 4 + 1][ar] = av.y;
        As[aq * 4 + 2][ar] = av.z; As[aq * 4 + 3][ar] = av.w;
        *(float4*)&Bs[bk][bc] = *(const float4*)&B[(size_t)(k0 + bk) * N + bx + bc];
        __syncthreads();
#pragma unroll
        for (int kk = 0; kk < 16; kk++) {
            float4 a4 = *(const float4*)&As[kk][ty * 4];
            ull b0 = *(const ull*)&Bs[kk][tx * 4];
            ull b1 = *(const ull*)&Bs[kk][tx * 4 + 2];
            ull s;
            s = f2pack(a4.x, a4.x); acc[0][0] = f2fma(s, b0, acc[0][0]); acc[0][1] = f2fma(s, b1, acc[0][1]);
            s = f2pack(a4.y, a4.y); acc[1][0] = f2fma(s, b0, acc[1][0]); acc[1][1] = f2fma(s, b1, acc[1][1]);
            s = f2pack(a4.z, a4.z); acc[2][0] = f2fma(s, b0, acc[2][0]); acc[2][1] = f2fma(s, b1, acc[2][1]);
            s = f2pack(a4.w, a4.w); acc[3][0] = f2fma(s, b0, acc[3][0]); acc[3][1] = f2fma(s, b1, acc[3][1]);
        }
    }
    float b0 = bias[bx + tx * 4], b1 = bias[bx + tx * 4 + 1];
    float b2 = bias[bx + tx * 4 + 2], b3 = bias[bx + tx * 4 + 3];
#pragma unroll
    for (int r = 0; r < 4; r++) {
        float o0, o1, o2, o3;
        f2unpack(acc[r][0], o0, o1);
        f2unpack(acc[r][1], o2, o3);
        o0 += b0; o1 += b1; o2 += b2; o3 += b3;
        if (act) {
            o0 = __fdividef(o0, 1.f + __expf(-o0));
            o1 = __fdividef(o1, 1.f + __expf(-o1));
            o2 = __fdividef(o2, 1.f + __expf(-o2));
            o3 = __fdividef(o3, 1.f + __expf(-o3));
        }
        *(float4*)&C[(size_t)(by + ty * 4 + r) * N + bx + tx * 4] = make_float4(o0, o1, o2, o3);
    }
}

// merged: h = silu(s@W1+b1)  (x-tiles 0..1)  and  qkv = s@Wd+bd  (x-tiles 2..7)
__global__ void __launch_bounds__(256)
k_gemm_hq(const float* __restrict__ s,
          const float* __restrict__ W1, const float* __restrict__ b1,
          const float* __restrict__ Wd, const float* __restrict__ bd,
          float* __restrict__ h, float* __restrict__ qkv)
{
    __shared__ __align__(16) float As[16][68];
    __shared__ __align__(16) float Bs[16][68];
    int bx2 = blockIdx.x, by = blockIdx.y * 64;
    if (bx2 < 2)
        gemm_tile(s, W1, b1, h,   128, 128, 1, bx2 * 64,       by, As, Bs);
    else
        gemm_tile(s, Wd, bd, qkv, 128, 384, 0, (bx2 - 2) * 64, by, As, Bs);
}

__global__ void __launch_bounds__(256)
k_gemm(const float* __restrict__ A, const float* __restrict__ B,
       const float* __restrict__ bias, float* __restrict__ C,
       int K, int N, int act)
{
    __shared__ __align__(16) float As[16][68];
    __shared__ __align__(16) float Bs[16][68];
    gemm_tile(A, B, bias, C, K, N, act, blockIdx.x * 64, blockIdx.y * 64, As, Bs);
}

// ---------------- per-graph attention ----------------
#define AT_SMEM 29952
__global__ void __launch_bounds__(256)
k_attn(const float* __restrict__ qkv, float* __restrict__ out_s)
{
    extern __shared__ float sm[];
    float* sQ  = sm;
    float* sKT = sm + 8448;
    float* sV  = sm + 17152;
    float* sP  = sm + 25600;
    const int g = blockIdx.x, tid = threadIdx.x;
    const int tx = tid & 15, ty = tid >> 4;

    const float* src = qkv + (size_t)g * 64 * 384;
    for (int idx = tid; idx < 64 * 384; idx += 256) {
        int r = idx / 384, col = idx - r * 384;
        float v = src[idx];
        if (col < 128)      sQ[r * 132 + col] = v;
        else if (col < 256) sKT[(col - 128) * 68 + r] = v;
        else                sV[r * 132 + (col - 256)] = v;
    }
    __syncthreads();

    {
        ull sa[4][2];
#pragma unroll
        for (int r = 0; r < 4; r++) { sa[r][0] = 0ull; sa[r][1] = 0ull; }
#pragma unroll 4
        for (int kk = 0; kk < 128; kk++) {
            ull b0 = *(const ull*)&sKT[kk * 68 + tx * 4];
            ull b1 = *(const ull*)&sKT[kk * 68 + tx * 4 + 2];
            float a0 = sQ[(ty * 4 + 0) * 132 + kk];
            float a1 = sQ[(ty * 4 + 1) * 132 + kk];
            float a2 = sQ[(ty * 4 + 2) * 132 + kk];
            float a3 = sQ[(ty * 4 + 3) * 132 + kk];
            ull s;
            s = f2pack(a0, a0); sa[0][0] = f2fma(s, b0, sa[0][0]); sa[0][1] = f2fma(s, b1, sa[0][1]);
            s = f2pack(a1, a1); sa[1][0] = f2fma(s, b0, sa[1][0]); sa[1][1] = f2fma(s, b1, sa[1][1]);
            s = f2pack(a2, a2); sa[2][0] = f2fma(s, b0, sa[2][0]); sa[2][1] = f2fma(s, b1, sa[2][1]);
            s = f2pack(a3, a3); sa[3][0] = f2fma(s, b0, sa[3][0]); sa[3][1] = f2fma(s, b1, sa[3][1]);
        }
        const float scale = 0.08838834764831845f;
#pragma unroll
        for (int r = 0; r < 4; r++) {
            float o0, o1, o2, o3;
            f2unpack(sa[r][0], o0, o1);
            f2unpack(sa[r][1], o2, o3);
            sP[(ty * 4 + r) * 68 + tx * 4 + 0] = o0 * scale;
            sP[(ty * 4 + r) * 68 + tx * 4 + 1] = o1 * scale;
            sP[(ty * 4 + r) * 68 + tx * 4 + 2] = o2 * scale;
            sP[(ty * 4 + r) * 68 + tx * 4 + 3] = o3 * scale;
        }
    }
    __syncthreads();

    if (tid < 64) {
        float* row = sP + tid * 68;
        float mx = row[0];
        for (int j = 1; j < 64; j++) mx = fmaxf(mx, row[j]);
        float sum = 0.f;
        for (int j = 0; j < 64; j++) { float e = __expf(row[j] - mx); row[j] = e; sum += e; }
        float inv = __fdividef(1.f, sum);
        for (int j = 0; j < 64; j++) row[j] *= inv;
    }
    __syncthreads();

    {
        ull aa[4][4];
#pragma unroll
        for (int r = 0; r < 4; r++)
#pragma unroll
            for (int p = 0; p < 4; p++) aa[r][p] = 0ull;
#pragma unroll 4
        for (int kk = 0; kk < 64; kk++) {
            ull b0 = *(const ull*)&sV[kk * 132 + tx * 8];
            ull b1 = *(const ull*)&sV[kk * 132 + tx * 8 + 2];
            ull b2 = *(const ull*)&sV[kk * 132 + tx * 8 + 4];
            ull b3 = *(const ull*)&sV[kk * 132 + tx * 8 + 6];
            float a0 = sP[(ty * 4 + 0) * 68 + kk];
            float a1 = sP[(ty * 4 + 1) * 68 + kk];
            float a2 = sP[(ty * 4 + 2) * 68 + kk];
            float a3 = sP[(ty * 4 + 3) * 68 + kk];
            ull s;
            s = f2pack(a0, a0); aa[0][0]=f2fma(s,b0,aa[0][0]); aa[0][1]=f2fma(s,b1,aa[0][1]); aa[0][2]=f2fma(s,b2,aa[0][2]); aa[0][3]=f2fma(s,b3,aa[0][3]);
            s = f2pack(a1, a1); aa[1][0]=f2fma(s,b0,aa[1][0]); aa[1][1]=f2fma(s,b1,aa[1][1]); aa[1][2]=f2fma(s,b2,aa[1][2]); aa[1][3]=f2fma(s,b3,aa[1][3]);
            s = f2pack(a2, a2); aa[2][0]=f2fma(s,b0,aa[2][0]); aa[2][1]=f2fma(s,b1,aa[2][1]); aa[2][2]=f2fma(s,b2,aa[2][2]); aa[2][3]=f2fma(s,b3,aa[2][3]);
            s = f2pack(a3, a3); aa[3][0]=f2fma(s,b0,aa[3][0]); aa[3][1]=f2fma(s,b1,aa[3][1]); aa[3][2]=f2fma(s,b2,aa[3][2]); aa[3][3]=f2fma(s,b3,aa[3][3]);
        }
#pragma unroll
        for (int r = 0; r < 4; r++) {
            int row = g * 64 + ty * 4 + r;
            float o[8];
            f2unpack(aa[r][0], o[0], o[1]);
            f2unpack(aa[r][1], o[2], o[3]);
            f2unpack(aa[r][2], o[4], o[5]);
            f2unpack(aa[r][3], o[6], o[7]);
            *(float4*)&out_s[(size_t)row * FEAT + tx * 8]     = make_float4(o[0], o[1], o[2], o[3]);
            *(float4*)&out_s[(size_t)row * FEAT + tx * 8 + 4] = make_float4(o[4], o[5], o[6], o[7]);
        }
    }
}

// ---------------- edge message pass (pipelined gathers) ----------------
#define EDGE_LOAD(DST, P0, P1, P2, VX, VY, VZ) do {            \
    const float* _ph = g_phi + (size_t)(DST) * 384;            \
    const float* _vt = g_vt  + (size_t)(DST) * 384;            \
    P0 = __ldg(_ph + c); P1 = __ldg(_ph + c + 128); P2 = __ldg(_ph + c + 256); \
    VX = __ldg(_vt + c); VY = __ldg(_vt + c + 128); VZ = __ldg(_vt + c + 256); \
} while (0)

#define EDGE_COMPUTE(JJ, Q0, Q1, Q2, WX, WY, WZ) do {          \
    float _env = senv[JJ];                                     \
    float _ux = sux[JJ], _uy = suy[JJ], _uz = suz[JJ];         \
    const ull* _tp = (const ull*)&st[JJ][0];                   \
    ull _t = _tp[0];                                           \
    ull _w0 = f2mul(_t, wp0[0]);                               \
    ull _w1 = f2mul(_t, wp1[0]);                               \
    ull _w2 = f2mul(_t, wp2[0]);                               \
    _Pragma("unroll")                                          \
    for (int _k = 1; _k < NRBF / 2; _k++) {                    \
        _t = _tp[_k];                                          \
        _w0 = f2fma(_t, wp0[_k], _w0);                         \
        _w1 = f2fma(_t, wp1[_k], _w1);                         \
        _w2 = f2fma(_t, wp2[_k], _w2);                         \
    }                                                          \
    float _l, _h;                                              \
    f2unpack(_w0, _l, _h); float _ws0 = fmaf(br0, _env, _l + _h); \
    f2unpack(_w1, _l, _h); float _ws1 = fmaf(br1, _env, _l + _h); \
    f2unpack(_w2, _l, _h); float _ws2 = fmaf(br2, _env, _l + _h); \
    float _a0 = (Q0) * _ws0, _a2 = (Q2) * _ws2;                \
    accs = fmaf((Q1), _ws1, accs);                             \
    avx = fmaf(_a2, _ux, fmaf(_a0, (WX), avx));                \
    avy = fmaf(_a2, _uy, fmaf(_a0, (WY), avy));                \
    avz = fmaf(_a2, _uz, fmaf(_a0, (WZ), avz));                \
} while (0)

__global__ void __launch_bounds__(128, 4)
k_edge(const float* __restrict__ r_ij, const int2* __restrict__ nbrs,
       const float* __restrict__ Wr, const float* __restrict__ br,
       float* __restrict__ out)
{
    const int c = threadIdx.x;

    ull wp0[NRBF / 2], wp1[NRBF / 2], wp2[NRBF / 2];
#pragma unroll
    for (int k = 0; k < NRBF / 2; k++) {
        wp0[k] = f2pack(__ldg(&Wr[(2 * k) * 384 + c]),       __ldg(&Wr[(2 * k + 1) * 384 + c]));
        wp1[k] = f2pack(__ldg(&Wr[(2 * k) * 384 + 128 + c]), __ldg(&Wr[(2 * k + 1) * 384 + 128 + c]));
        wp2[k] = f2pack(__ldg(&Wr[(2 * k) * 384 + 256 + c]), __ldg(&Wr[(2 * k + 1) * 384 + 256 + c]));
    }
    const float br0 = __ldg(&br[c]), br1 = __ldg(&br[128 + c]), br2 = __ldg(&br[256 + c]);

    __shared__ __align__(16) float st[32][NRBF];
    __shared__ float senv[32], sux[32], suy[32], suz[32];
    __shared__ int sdst[32];

    for (int a = 0; a < APB; a++) {
        const int i = blockIdx.x * APB + a;
        const int deg = g_cnt[i], start = g_off[i];
        float accs = 0.f, avx = 0.f, avy = 0.f, avz = 0.f;

        for (int base = 0; base < deg; base += 32) {
            int m = min(32, deg - base);
            __syncthreads();
            if (c < m) {
                int e = g_eid[start + base + c];
                sdst[c] = nbrs[e].y;
                float rx = r_ij[3 * e], ry = r_ij[3 * e + 1], rz = r_ij[3 * e + 2];
                float d = sqrtf(fmaf(rx, rx, fmaf(ry, ry, rz * rz)));
                bool in = d < 5.0f;
                float invd = in ? __fdividef(1.f, d) : 0.f;
                float s1, c1;
                __sincosf(0.6283185307179586f * d, &s1, &c1);
                float env = in ? fmaf(0.5f, c1, 0.5f) : 0.f;
                float einv = env * invd;
                senv[c] = env;
                sux[c] = rx * invd; suy[c] = ry * invd; suz[c] = rz * invd;
                float c2 = 2.f * c1, sp = 0.f, sc = s1;
                st[c][0] = s1 * einv;
#pragma unroll
                for (int n = 1; n < NRBF; n++) {
                    float sn = fmaf(c2, sc, -sp);
                    sp = sc; sc = sn;
                    st[c][n] = sn * einv;
                }
            }
            __syncthreads();

            // software-pipelined consumer: depth-2 prefetch of phi/vt gathers
            float pA0, pA1, pA2, vAx, vAy, vAz;
            float pB0, pB1, pB2, vBx, vBy, vBz;
            EDGE_LOAD(sdst[0], pA0, pA1, pA2, vAx, vAy, vAz);
            if (m > 1) EDGE_LOAD(sdst[1], pB0, pB1, pB2, vBx, vBy, vBz);
            else { pB0=pB1=pB2=vBx=vBy=vBz=0.f; }

            int j = 0;
            for (; j + 1 < m; j += 2) {
                {   // even: consume A, refill A with j+2
                    float q0 = pA0, q1 = pA1, q2 = pA2;
                    float wx = vAx, wy = vAy, wz = vAz;
                    if (j + 2 < m) EDGE_LOAD(sdst[j + 2], pA0, pA1, pA2, vAx, vAy, vAz);
                    EDGE_COMPUTE(j, q0, q1, q2, wx, wy, wz);
                }
                {   // odd: consume B, refill B with j+3
                    float q0 = pB0, q1 = pB1, q2 = pB2;
                    float wx = vBx, wy = vBy, wz = vBz;
                    if (j + 3 < m) EDGE_LOAD(sdst[j + 3], pB0, pB1, pB2, vBx, vBy, vBz);
                    EDGE_COMPUTE(j + 1, q0, q1, q2, wx, wy, wz);
                }
            }
            if (j < m) {
                EDGE_COMPUTE(j, pA0, pA1, pA2, vAx, vAy, vAz);
            }
        }
        size_t idx = (size_t)i * FEAT + c;
        out[idx] += accs;
        float* outv = out + (size_t)NATOMS * FEAT;
        outv[idx * 3 + 0] = avx;
        outv[idx * 3 + 1] = avy;
        outv[idx * 3 + 2] = avz;
    }
}

// ---------------- launch ----------------
extern "C" void kernel_launch(void* const* d_in, const int* in_sizes, int n_in,
                              void* d_out, int out_size)
{
    const float* s_j  = (const float*)d_in[0];
    const float* v_j  = (const float*)d_in[1];
    const float* r_ij = (const float*)d_in[2];
    const int*   nbrs = (const int*)  d_in[3];
    const float* W1 = (const float*)d_in[5];
    const float* b1 = (const float*)d_in[6];
    const float* W2 = (const float*)d_in[7];
    const float* b2 = (const float*)d_in[8];
    const float* Wr = (const float*)d_in[9];
    const float* br = (const float*)d_in[10];
    const float* Wd = (const float*)d_in[11];
    const float* bd = (const float*)d_in[12];
    float* out = (float*)d_out;

    float* g_h_p;   cudaGetSymbolAddress((void**)&g_h_p,   g_h);
    float* g_phi_p; cudaGetSymbolAddress((void**)&g_phi_p, g_phi);
    float* g_qkv_p; cudaGetSymbolAddress((void**)&g_qkv_p, g_qkv);
    int*   g_cnt_p; cudaGetSymbolAddress((void**)&g_cnt_p, g_cnt);

    cudaFuncSetAttribute(k_attn, cudaFuncAttributeMaxDynamicSharedMemorySize,
                         AT_SMEM * sizeof(float));

    cudaMemsetAsync(g_cnt_p, 0, NATOMS * sizeof(int));
    k_hist<<<NEDGES / 256, 256>>>((const int2*)nbrs);
    k_scan<<<1, 1024>>>();
    // 1024 scatter blocks + NATOMS/2 = 4096 vt blocks (2 atoms per block)
    k_sv<<<1024 + NATOMS / 2, 256>>>((const int2*)nbrs, v_j);
    dim3 ghq(8, 128);
    k_gemm_hq<<<ghq, 256>>>(s_j, W1, b1, Wd, bd, g_h_p, g_qkv_p);
    dim3 gp(6, 128);
    k_gemm<<<gp, 256>>>(g_h_p, W2, b2, g_phi_p, 128, 384, 0);
    k_attn<<<NGRAPHS, 256, AT_SMEM * sizeof(float)>>>(g_qkv_p, out);
    k_edge<<<NATOMS / APB, 128>>>(r_ij, (const int2*)nbrs, Wr, br, out);
}